// round 11
// baseline (speedup 1.0000x reference)
#include <cuda_runtime.h>
#include <cuda_bf16.h>
#include <math.h>
#include <stdint.h>

// ===========================================================================
// Static scratch. Branch 0 = q (B=4096 rows), branch 1 = k (N=8192 rows).
// Activations: bf16 hi (main term) + e4m3 hi + e4m3 lo*256 (cross terms).
// Stats: [branch][slot 0..3][1024]; bias: [branch][layer][1024]; pre-zeroed.
// ===========================================================================
__device__ float g_sum[2 * 4 * 1024];
__device__ float g_sumsq[2 * 4 * 1024];
__device__ float g_bias2[2 * 3 * 1024];
__device__ float g_k2[8192];

__device__ __nv_bfloat16 g_Q1h[4096 * 1024], g_Q2h[4096 * 1024];
__device__ uint8_t g_Q18h[4096 * 1024], g_Q18l[4096 * 1024];
__device__ uint8_t g_Q28h[4096 * 1024], g_Q28l[4096 * 1024];
__device__ __nv_bfloat16 g_P1h[8192 * 1024], g_P2h[8192 * 1024];
__device__ uint8_t g_P18h[8192 * 1024], g_P18l[8192 * 1024];
__device__ uint8_t g_P28h[8192 * 1024], g_P28l[8192 * 1024];
__device__ __nv_bfloat16 g_W0h[1024 * 1024], g_W1h[1024 * 1024];
__device__ uint8_t g_W08h[1024 * 1024], g_W08l[1024 * 1024];
__device__ uint8_t g_W18h[1024 * 1024], g_W18l[1024 * 1024];
__device__ __nv_bfloat16 g_qh[4096 * 256], g_kh[8192 * 256];
__device__ uint8_t g_q8h[4096 * 256], g_q8l[4096 * 256];
__device__ uint8_t g_k8h[8192 * 256], g_k8l[8192 * 256];
__device__ float g_pm[4096 * 64], g_pl[4096 * 64], g_pw[4096 * 64];

// ===========================================================================
// fp8 helpers
// ===========================================================================
__device__ __forceinline__ uint16_t pack_e4m3(float hiByte, float loByte) {
    uint16_t r;
    asm("cvt.rn.satfinite.e4m3x2.f32 %0, %1, %2;" : "=h"(r) : "f"(hiByte), "f"(loByte));
    return r;  // bits[7:0] = cvt(loByte), bits[15:8] = cvt(hiByte)
}
__device__ __forceinline__ uint8_t to_e4m3(float v) {
    return (uint8_t)(pack_e4m3(0.f, v) & 0xFF);
}

// ===========================================================================
// Prep kernels
// ===========================================================================
__global__ void zero_all() {
    int i = blockIdx.x * blockDim.x + threadIdx.x;   // 0..8191
    g_sum[i] = 0.f;
    g_sumsq[i] = 0.f;
    g_k2[i] = 0.f;
    if (i < 6144) g_bias2[i] = 0.f;
}

__global__ void split_stats_b(const float* __restrict__ X,
                              __nv_bfloat16* __restrict__ hi,
                              uint8_t* __restrict__ h8,
                              uint8_t* __restrict__ l8,
                              int R, int Din, int br) {
    int c = blockIdx.x * blockDim.x + threadIdx.x;
    if (c >= Din) return;
    int chunk = R / gridDim.y;
    int r0 = blockIdx.y * chunk;
    float s = 0.f, s2 = 0.f;
    for (int r = r0; r < r0 + chunk; ++r) {
        size_t i = (size_t)r * Din + c;
        float v = X[i];
        __nv_bfloat16 h = __float2bfloat16(v);
        hi[i] = h;
        float lo = v - __bfloat162float(h);
        h8[i] = to_e4m3(v);
        l8[i] = to_e4m3(lo * 256.f);
        s += v;
        s2 = fmaf(v, v, s2);
    }
    atomicAdd(&g_sum[br * 4096 + c], s);
    atomicAdd(&g_sumsq[br * 4096 + c], s2);
}

// Fused BN finalize + WT transpose/scale/split (bf16 hi + fp8 hi/lo) + bias2
__global__ void wprep_fused(const float* __restrict__ W, int Din, int Dout,
                            __nv_bfloat16* __restrict__ WTh,
                            uint8_t* __restrict__ WT8h,
                            uint8_t* __restrict__ WT8l,
                            int br, int layer, int R,
                            const float* __restrict__ gam,
                            const float* __restrict__ bet) {
    __shared__ float tile[32][33];
    __shared__ float sbias[8][32];
    __shared__ float sa[32], sdd[32];
    int k0 = blockIdx.y * 32, n0 = blockIdx.x * 32;
    int tx = threadIdx.x, ty = threadIdx.y;

    if (ty == 0) {
        int c = k0 + tx;
        int offs = (br * 4 + layer) * 1024;
        float inv = 1.0f / (float)R;
        float mean = g_sum[offs + c] * inv;
        float var = g_sumsq[offs + c] * inv - mean * mean;
        float a = gam[c] * rsqrtf(var + 1e-5f);
        sa[tx] = a;
        sdd[tx] = bet[c] - mean * a;
    }
    __syncthreads();

    float bp = 0.f;
    for (int i = ty; i < 32; i += 8) {
        float w = W[(size_t)(k0 + i) * Dout + n0 + tx];
        tile[i][tx] = sa[i] * w;
        bp = fmaf(sdd[i], w, bp);
    }
    sbias[ty][tx] = bp;
    __syncthreads();
    if (ty == 0) {
        float s = 0.f;
#pragma unroll
        for (int j = 0; j < 8; ++j) s += sbias[j][tx];
        atomicAdd(&g_bias2[(br * 3 + layer) * 1024 + n0 + tx], s);
    }
    for (int i = ty; i < 32; i += 8) {
        float v = tile[tx][i];
        size_t idx = (size_t)(n0 + i) * Din + (k0 + tx);
        __nv_bfloat16 h = __float2bfloat16(v);
        WTh[idx] = h;
        float lo = v - __bfloat162float(h);
        WT8h[idx] = to_e4m3(v);
        WT8l[idx] = to_e4m3(lo * 256.f);
    }
}

// ===========================================================================
// GEMM: CTA 128x128, K-tile 64, 2-stage cp.async, 8 warps (2x4), warp tile
// 64x32. Main term: bf16 m16n8k16 (hi*hi). Cross terms: e4m3 m16n8k32
// (hi8*lo8 + lo8*hi8, lo pre-scaled by 2^8) into a second accumulator.
// Result = acc + acc_c / 256.
// ===========================================================================
#define LDB 144                       // bf16 tile row stride (128B data + 16 pad)
#define LD8 80                        // fp8 tile row stride (64B data + 16 pad)
#define BF_TILE_B (128 * LDB)         // 18432
#define F8_TILE_B (128 * LD8)         // 10240
#define STAGE_B (2 * BF_TILE_B + 4 * F8_TILE_B)   // 77824
#define GEMM_SMEM (2 * STAGE_B)                    // 155648

__device__ __forceinline__ void mma_bf16(float* d, const uint32_t* a, const uint32_t* b) {
    asm volatile("mma.sync.aligned.m16n8k16.row.col.f32.bf16.bf16.f32 "
        "{%0,%1,%2,%3}, {%4,%5,%6,%7}, {%8,%9}, {%0,%1,%2,%3};"
        : "+f"(d[0]), "+f"(d[1]), "+f"(d[2]), "+f"(d[3])
        : "r"(a[0]), "r"(a[1]), "r"(a[2]), "r"(a[3]), "r"(b[0]), "r"(b[1]));
}
__device__ __forceinline__ void mma_fp8(float* d, const uint32_t* a, const uint32_t* b) {
    asm volatile("mma.sync.aligned.m16n8k32.row.col.f32.e4m3.e4m3.f32 "
        "{%0,%1,%2,%3}, {%4,%5,%6,%7}, {%8,%9}, {%0,%1,%2,%3};"
        : "+f"(d[0]), "+f"(d[1]), "+f"(d[2]), "+f"(d[3])
        : "r"(a[0]), "r"(a[1]), "r"(a[2]), "r"(a[3]), "r"(b[0]), "r"(b[1]));
}

// Fill stage s with K-tile t: 4096 16B chunks, 256 threads x 16.
#define FILL_TILE(t, s)                                                        \
    do {                                                                       \
        char* base_ = smem + (s) * STAGE_B;                                    \
        const int k0_ = (t) << 6;                                              \
        _Pragma("unroll")                                                      \
        for (int l_ = 0; l_ < 16; ++l_) {                                      \
            int id_ = tid + (l_ << 8);                                         \
            if (id_ < 2048) {                                                  \
                int which_ = id_ >> 10;                                        \
                int e_ = id_ & 1023;                                           \
                int row_ = e_ >> 3, c16_ = e_ & 7;                             \
                const __nv_bfloat16* src_ = which_ ? Bh : Ah;                  \
                int grow_ = (which_ ? n0 : m0) + row_;                         \
                const char* gp_ = (const char*)(src_ + (size_t)grow_ * K + k0_) + (c16_ << 4); \
                uint32_t sp_ = (uint32_t)__cvta_generic_to_shared(             \
                    base_ + which_ * BF_TILE_B + row_ * LDB + (c16_ << 4));    \
                asm volatile("cp.async.cg.shared.global [%0], [%1], 16;" :: "r"(sp_), "l"(gp_)); \
            } else {                                                           \
                int f_ = id_ - 2048;                                           \
                int which_ = f_ >> 9;                                          \
                int e_ = f_ & 511;                                             \
                int row_ = e_ >> 2, c16_ = e_ & 3;                             \
                const uint8_t* src_ = (which_ == 0) ? A8h : (which_ == 1) ? A8l \
                                     : (which_ == 2) ? B8h : B8l;              \
                int grow_ = ((which_ < 2) ? m0 : n0) + row_;                   \
                const char* gp_ = (const char*)(src_ + (size_t)grow_ * K + k0_) + (c16_ << 4); \
                uint32_t sp_ = (uint32_t)__cvta_generic_to_shared(             \
                    base_ + 2 * BF_TILE_B + which_ * F8_TILE_B + row_ * LD8 + (c16_ << 4)); \
                asm volatile("cp.async.cg.shared.global [%0], [%1], 16;" :: "r"(sp_), "l"(gp_)); \
            }                                                                  \
        }                                                                      \
        asm volatile("cp.async.commit_group;");                                \
    } while (0)

#define MMA_MAINLOOP()                                                         \
    do {                                                                       \
        FILL_TILE(0, 0);                                                       \
        for (int t = 0; t < T; ++t) {                                          \
            if (t + 1 < T) {                                                   \
                FILL_TILE(t + 1, (t + 1) & 1);                                 \
                asm volatile("cp.async.wait_group 1;");                        \
            } else {                                                           \
                asm volatile("cp.async.wait_group 0;");                        \
            }                                                                  \
            __syncthreads();                                                   \
            const char* st_ = smem + (t & 1) * STAGE_B;                        \
            /* main term: bf16 hi*hi, 4 k16 steps */                           \
            _Pragma("unroll")                                                  \
            for (int kk = 0; kk < 4; ++kk) {                                   \
                const int kb_ = kk * 32 + cc * 2;                              \
                uint32_t bh_[4][2];                                            \
                _Pragma("unroll")                                              \
                for (int nt = 0; nt < 4; ++nt) {                               \
                    const char* pB_ = st_ + BF_TILE_B + (wn * 32 + nt * 8 + g) * LDB + kb_; \
                    bh_[nt][0] = *(const uint32_t*)pB_;                        \
                    bh_[nt][1] = *(const uint32_t*)(pB_ + 16);                 \
                }                                                              \
                _Pragma("unroll")                                              \
                for (int mt = 0; mt < 4; ++mt) {                               \
                    const char* pA_ = st_ + (wm * 64 + mt * 16 + g) * LDB + kb_; \
                    uint32_t ah_[4];                                           \
                    ah_[0] = *(const uint32_t*)pA_;                            \
                    ah_[1] = *(const uint32_t*)(pA_ + 8 * LDB);                \
                    ah_[2] = *(const uint32_t*)(pA_ + 16);                     \
                    ah_[3] = *(const uint32_t*)(pA_ + 8 * LDB + 16);           \
                    _Pragma("unroll")                                          \
                    for (int nt = 0; nt < 4; ++nt)                             \
                        mma_bf16(acc[mt][nt], ah_, bh_[nt]);                   \
                }                                                              \
            }                                                                  \
            /* cross terms: e4m3 k32 steps, scaled 2^8, into acc_c */          \
            _Pragma("unroll")                                                  \
            for (int ks = 0; ks < 2; ++ks) {                                   \
                const int kb_ = ks * 32 + (lane & 3) * 4;                      \
                uint32_t b8h_[4][2], b8l_[4][2];                               \
                _Pragma("unroll")                                              \
                for (int nt = 0; nt < 4; ++nt) {                               \
                    const char* pBh_ = st_ + 2 * BF_TILE_B + 2 * F8_TILE_B     \
                                     + (wn * 32 + nt * 8 + g) * LD8 + kb_;     \
                    b8h_[nt][0] = *(const uint32_t*)pBh_;                      \
                    b8h_[nt][1] = *(const uint32_t*)(pBh_ + 16);               \
                    b8l_[nt][0] = *(const uint32_t*)(pBh_ + F8_TILE_B);        \
                    b8l_[nt][1] = *(const uint32_t*)(pBh_ + F8_TILE_B + 16);   \
                }                                                              \
                _Pragma("unroll")                                              \
                for (int mt = 0; mt < 4; ++mt) {                               \
                    const char* pAh_ = st_ + 2 * BF_TILE_B                     \
                                     + (wm * 64 + mt * 16 + g) * LD8 + kb_;    \
                    uint32_t a8h_[4], a8l_[4];                                 \
                    a8h_[0] = *(const uint32_t*)pAh_;                          \
                    a8h_[1] = *(const uint32_t*)(pAh_ + 8 * LD8);              \
                    a8h_[2] = *(const uint32_t*)(pAh_ + 16);                   \
                    a8h_[3] = *(const uint32_t*)(pAh_ + 8 * LD8 + 16);         \
                    a8l_[0] = *(const uint32_t*)(pAh_ + F8_TILE_B);            \
                    a8l_[1] = *(const uint32_t*)(pAh_ + F8_TILE_B + 8 * LD8);  \
                    a8l_[2] = *(const uint32_t*)(pAh_ + F8_TILE_B + 16);       \
                    a8l_[3] = *(const uint32_t*)(pAh_ + F8_TILE_B + 8 * LD8 + 16); \
                    _Pragma("unroll")                                          \
                    for (int nt = 0; nt < 4; ++nt) {                           \
                        mma_fp8(acc_c[mt][nt], a8h_, b8l_[nt]);                \
                        mma_fp8(acc_c[mt][nt], a8l_, b8h_[nt]);                \
                    }                                                          \
                }                                                              \
            }                                                                  \
            __syncthreads();                                                   \
        }                                                                      \
    } while (0)

#define GEMM_THREAD_IDS()                                                      \
    const int tid = threadIdx.x;                                               \
    const int wid = tid >> 5, lane = tid & 31;                                 \
    const int g = lane >> 2;                                                   \
    const int cc = (lane & 3) * 2;                                             \
    const int wm = wid >> 2, wn = wid & 3;                                     \
    float acc[4][4][4], acc_c[4][4][4];                                        \
    _Pragma("unroll")                                                          \
    for (int i = 0; i < 4; ++i)                                                \
        _Pragma("unroll")                                                      \
        for (int j = 0; j < 4; ++j)                                            \
            _Pragma("unroll")                                                  \
            for (int r = 0; r < 4; ++r) { acc[i][j][r] = 0.f; acc_c[i][j][r] = 0.f; }

#define CSCALE 0.00390625f   // 2^-8

// ===========================================================================
// Trunk GEMM. Y = tanh(acc + acc_c/256 + bias). Emits bf16 hi + fp8 hi/lo.
// accum 1: col stats -> slot layer+1; accum 2: row sumsq -> g_k2.
// ===========================================================================
__global__ __launch_bounds__(256, 1) void gemm_trunk(
    const __nv_bfloat16* __restrict__ Ah,
    const uint8_t* __restrict__ A8h, const uint8_t* __restrict__ A8l,
    const __nv_bfloat16* __restrict__ Bh,
    const uint8_t* __restrict__ B8h, const uint8_t* __restrict__ B8l,
    const float* __restrict__ bvec,
    int K, int ldOut, int accum, int br, int layer,
    __nv_bfloat16* __restrict__ Yh,
    uint8_t* __restrict__ Y8h, uint8_t* __restrict__ Y8l)
{
    extern __shared__ __align__(16) char smem[];
    GEMM_THREAD_IDS();
    const int m0 = blockIdx.y * 128, n0 = blockIdx.x * 128;
    const int T = K >> 6;
    const float* bias = g_bias2 + (br * 3 + layer) * 1024;

    MMA_MAINLOOP();

    float* s_sum = (float*)smem;
    float* s_sq  = (float*)smem + 128;
    if (accum) {
        if (tid < 128) { s_sum[tid] = 0.f; s_sq[tid] = 0.f; }
        __syncthreads();
    }

#pragma unroll
    for (int mt = 0; mt < 4; ++mt) {
#pragma unroll
        for (int nt = 0; nt < 4; ++nt) {
            int row = m0 + wm * 64 + mt * 16 + g;
            int col = n0 + wn * 32 + nt * 8 + cc;
            float* a = acc[mt][nt];
            float* c = acc_c[mt][nt];
            float bA = bias[col] + bvec[col];
            float bB = bias[col + 1] + bvec[col + 1];
#pragma unroll
            for (int h = 0; h < 2; ++h) {
                int r = row + h * 8;
                float v0 = tanhf(fmaf(c[h * 2 + 0], CSCALE, a[h * 2 + 0]) + bA);
                float v1 = tanhf(fmaf(c[h * 2 + 1], CSCALE, a[h * 2 + 1]) + bB);
                a[h * 2 + 0] = v0;
                a[h * 2 + 1] = v1;
                __nv_bfloat162 hp;
                hp.x = __float2bfloat16(v0);
                hp.y = __float2bfloat16(v1);
                float lo0 = (v0 - __bfloat162float(hp.x)) * 256.f;
                float lo1 = (v1 - __bfloat162float(hp.y)) * 256.f;
                size_t o = (size_t)r * ldOut + col;
                *(uint32_t*)(Yh + o) = *(uint32_t*)&hp;
                *(uint16_t*)(Y8h + o) = pack_e4m3(v1, v0);
                *(uint16_t*)(Y8l + o) = pack_e4m3(lo1, lo0);
            }
        }
    }

    if (accum == 1) {
#pragma unroll
        for (int nt = 0; nt < 4; ++nt) {
            int lc = wn * 32 + nt * 8 + cc;
            float s0 = 0.f, q0 = 0.f, s1 = 0.f, q1 = 0.f;
#pragma unroll
            for (int mt = 0; mt < 4; ++mt) {
                float* a = acc[mt][nt];
#pragma unroll
                for (int h = 0; h < 2; ++h) {
                    s0 += a[h * 2 + 0]; q0 = fmaf(a[h * 2 + 0], a[h * 2 + 0], q0);
                    s1 += a[h * 2 + 1]; q1 = fmaf(a[h * 2 + 1], a[h * 2 + 1], q1);
                }
            }
            atomicAdd(&s_sum[lc], s0);     atomicAdd(&s_sq[lc], q0);
            atomicAdd(&s_sum[lc + 1], s1); atomicAdd(&s_sq[lc + 1], q1);
        }
        __syncthreads();
        if (tid < 128) {
            int offs = (br * 4 + layer + 1) * 1024 + n0 + tid;
            atomicAdd(&g_sum[offs], s_sum[tid]);
            atomicAdd(&g_sumsq[offs], s_sq[tid]);
        }
    } else if (accum == 2) {
#pragma unroll
        for (int mt = 0; mt < 4; ++mt) {
#pragma unroll
            for (int h = 0; h < 2; ++h) {
                int lr = wm * 64 + mt * 16 + h * 8 + g;
                float s = 0.f;
#pragma unroll
                for (int nt = 0; nt < 4; ++nt) {
                    float v0 = acc[mt][nt][h * 2 + 0];
                    float v1 = acc[mt][nt][h * 2 + 1];
                    s = fmaf(v0, v0, s);
                    s = fmaf(v1, v1, s);
                }
                atomicAdd(&s_sum[lr], s);
            }
        }
        __syncthreads();
        if (tid < 128) atomicAdd(&g_k2[m0 + tid], s_sum[tid]);
    }
}

// ===========================================================================
// Flash sim+softmax: logits = 2*(acc + acc_c/256) - k2; partial softmax
// with y-weighting -> (max, expsum, wsum) per row per key-split.
// ===========================================================================
__global__ __launch_bounds__(256, 1) void sim_flash(
    const __nv_bfloat16* __restrict__ Ah,
    const uint8_t* __restrict__ A8h, const uint8_t* __restrict__ A8l,
    const __nv_bfloat16* __restrict__ Bh,
    const uint8_t* __restrict__ B8h, const uint8_t* __restrict__ B8l,
    const float* __restrict__ y, int K, int nsplit)
{
    extern __shared__ __align__(16) char smem[];
    GEMM_THREAD_IDS();
    const int m0 = blockIdx.y * 128, n0 = blockIdx.x * 128;
    const int T = K >> 6;
    MMA_MAINLOOP();

    float yv[4][2], k2v[4][2];
#pragma unroll
    for (int nt = 0; nt < 4; ++nt) {
        int col = n0 + wn * 32 + nt * 8 + cc;
        yv[nt][0] = y[col];     yv[nt][1] = y[col + 1];
        k2v[nt][0] = g_k2[col]; k2v[nt][1] = g_k2[col + 1];
    }

    float* red = (float*)smem;
#pragma unroll
    for (int mt = 0; mt < 4; ++mt) {
#pragma unroll
        for (int h = 0; h < 2; ++h) {
            float lg[4][2];
            float mx = -3.4e38f;
#pragma unroll
            for (int nt = 0; nt < 4; ++nt) {
#pragma unroll
                for (int c2 = 0; c2 < 2; ++c2) {
                    float d = fmaf(acc_c[mt][nt][h * 2 + c2], CSCALE, acc[mt][nt][h * 2 + c2]);
                    float v = 2.f * d - k2v[nt][c2];
                    lg[nt][c2] = v;
                    mx = fmaxf(mx, v);
                }
            }
            mx = fmaxf(mx, __shfl_xor_sync(0xFFFFFFFF, mx, 1));
            mx = fmaxf(mx, __shfl_xor_sync(0xFFFFFFFF, mx, 2));
            float s = 0.f, w = 0.f;
#pragma unroll
            for (int nt = 0; nt < 4; ++nt) {
#pragma unroll
                for (int c2 = 0; c2 < 2; ++c2) {
                    float e = __expf(lg[nt][c2] - mx);
                    s += e;
                    w = fmaf(e, yv[nt][c2], w);
                }
            }
            s += __shfl_xor_sync(0xFFFFFFFF, s, 1);
            s += __shfl_xor_sync(0xFFFFFFFF, s, 2);
            w += __shfl_xor_sync(0xFFFFFFFF, w, 1);
            w += __shfl_xor_sync(0xFFFFFFFF, w, 2);
            if ((lane & 3) == 0) {
                int lr = wm * 64 + mt * 16 + h * 8 + g;
                red[(lr * 4 + wn) * 3 + 0] = mx;
                red[(lr * 4 + wn) * 3 + 1] = s;
                red[(lr * 4 + wn) * 3 + 2] = w;
            }
        }
    }
    __syncthreads();
    if (tid < 128) {
        float M = -3.4e38f;
#pragma unroll
        for (int j = 0; j < 4; ++j) M = fmaxf(M, red[(tid * 4 + j) * 3 + 0]);
        float L = 0.f, W = 0.f;
#pragma unroll
        for (int j = 0; j < 4; ++j) {
            float e = __expf(red[(tid * 4 + j) * 3 + 0] - M);
            L = fmaf(red[(tid * 4 + j) * 3 + 1], e, L);
            W = fmaf(red[(tid * 4 + j) * 3 + 2], e, W);
        }
        size_t idx = (size_t)(m0 + tid) * nsplit + blockIdx.x;
        g_pm[idx] = M;
        g_pl[idx] = L;
        g_pw[idx] = W;
    }
}

__global__ void combine_out(float* __restrict__ out, int S) {
    int row = blockIdx.x * 8 + (threadIdx.x >> 5);
    int lane = threadIdx.x & 31;
    size_t base = (size_t)row * S;
    float m1 = g_pm[base + lane], m2 = g_pm[base + lane + 32];
    float l1 = g_pl[base + lane], l2 = g_pl[base + lane + 32];
    float w1 = g_pw[base + lane], w2 = g_pw[base + lane + 32];
    float M = fmaxf(m1, m2);
#pragma unroll
    for (int o = 16; o > 0; o >>= 1)
        M = fmaxf(M, __shfl_xor_sync(0xFFFFFFFF, M, o));
    float L = l1 * __expf(m1 - M) + l2 * __expf(m2 - M);
    float W = w1 * __expf(m1 - M) + w2 * __expf(m2 - M);
#pragma unroll
    for (int o = 16; o > 0; o >>= 1) {
        L += __shfl_xor_sync(0xFFFFFFFF, L, o);
        W += __shfl_xor_sync(0xFFFFFFFF, W, o);
    }
    if (lane == 0) {
        float r = W / L;
        out[row] = fminf(fmaxf(r, 0.f), 1.f);
    }
}

// ===========================================================================
// Host launcher — fork/join two streams (q on capture stream, k on s2)
// ===========================================================================
extern "C" void kernel_launch(void* const* d_in, const int* in_sizes, int n_in,
                              void* d_out, int out_size)
{
    const float* x   = (const float*)d_in[0];
    const float* xn  = (const float*)d_in[1];
    const float* y   = (const float*)d_in[2];
    const float* Ws[3] = {(const float*)d_in[3], (const float*)d_in[7], (const float*)d_in[11]};
    const float* bs[3] = {(const float*)d_in[4], (const float*)d_in[8], (const float*)d_in[12]};
    const float* gs[3] = {(const float*)d_in[5], (const float*)d_in[9], (const float*)d_in[13]};
    const float* es[3] = {(const float*)d_in[6], (const float*)d_in[10], (const float*)d_in[14]};

    const int D  = in_sizes[5];
    const int B  = in_sizes[0] / D;      // 4096
    const int N  = in_sizes[2];          // 8192
    const int dims[4] = {D, in_sizes[4], in_sizes[8], in_sizes[12]};

    __nv_bfloat16 *q1h, *q2h, *p1h, *p2h, *w0h, *w1h, *qh, *kh;
    uint8_t *q18h, *q18l, *q28h, *q28l, *p18h, *p18l, *p28h, *p28l;
    uint8_t *w08h, *w08l, *w18h, *w18l, *q8h, *q8l, *k8h, *k8l;
    cudaGetSymbolAddress((void**)&q1h, g_Q1h);   cudaGetSymbolAddress((void**)&q2h, g_Q2h);
    cudaGetSymbolAddress((void**)&q18h, g_Q18h); cudaGetSymbolAddress((void**)&q18l, g_Q18l);
    cudaGetSymbolAddress((void**)&q28h, g_Q28h); cudaGetSymbolAddress((void**)&q28l, g_Q28l);
    cudaGetSymbolAddress((void**)&p1h, g_P1h);   cudaGetSymbolAddress((void**)&p2h, g_P2h);
    cudaGetSymbolAddress((void**)&p18h, g_P18h); cudaGetSymbolAddress((void**)&p18l, g_P18l);
    cudaGetSymbolAddress((void**)&p28h, g_P28h); cudaGetSymbolAddress((void**)&p28l, g_P28l);
    cudaGetSymbolAddress((void**)&w0h, g_W0h);   cudaGetSymbolAddress((void**)&w1h, g_W1h);
    cudaGetSymbolAddress((void**)&w08h, g_W08h); cudaGetSymbolAddress((void**)&w08l, g_W08l);
    cudaGetSymbolAddress((void**)&w18h, g_W18h); cudaGetSymbolAddress((void**)&w18l, g_W18l);
    cudaGetSymbolAddress((void**)&qh, g_qh);     cudaGetSymbolAddress((void**)&kh, g_kh);
    cudaGetSymbolAddress((void**)&q8h, g_q8h);   cudaGetSymbolAddress((void**)&q8l, g_q8l);
    cudaGetSymbolAddress((void**)&k8h, g_k8h);   cudaGetSymbolAddress((void**)&k8l, g_k8l);

    cudaFuncSetAttribute(gemm_trunk, cudaFuncAttributeMaxDynamicSharedMemorySize, GEMM_SMEM);
    cudaFuncSetAttribute(sim_flash, cudaFuncAttributeMaxDynamicSharedMemorySize, GEMM_SMEM);

    static cudaStream_t s2 = nullptr;
    static cudaEvent_t evFork = nullptr, evJoin = nullptr;
    if (s2 == nullptr) {
        cudaStreamCreateWithFlags(&s2, cudaStreamNonBlocking);
        cudaEventCreateWithFlags(&evFork, cudaEventDisableTiming);
        cudaEventCreateWithFlags(&evJoin, cudaEventDisableTiming);
    }

    zero_all<<<32, 256>>>();
    cudaEventRecord(evFork, 0);
    cudaStreamWaitEvent(s2, evFork, 0);

    split_stats_b<<<dim3(D / 256, 64), 256>>>(x, q1h, q18h, q18l, B, D, 0);
    split_stats_b<<<dim3(D / 256, 64), 256, 0, s2>>>(xn, p1h, p18h, p18l, N, D, 1);

    // ping-pong per branch: {bf16 hi, fp8 hi, fp8 lo}
    __nv_bfloat16 *qa_h = q1h, *qb_h = q2h;
    uint8_t *qa_8h = q18h, *qa_8l = q18l, *qb_8h = q28h, *qb_8l = q28l;
    __nv_bfloat16 *ka_h = p1h, *kb_h = p2h;
    uint8_t *ka_8h = p18h, *ka_8l = p18l, *kb_8h = p28h, *kb_8l = p28l;

    for (int i = 0; i < 3; ++i) {
        int Din = dims[i], Dout = dims[i + 1];
        int nx = Dout / 128;
        int accum_q = (i < 2) ? 1 : 0;
        int accum_k = (i < 2) ? 1 : 2;

        // q branch (default stream)
        wprep_fused<<<dim3(Dout / 32, Din / 32), dim3(32, 8)>>>(
            Ws[i], Din, Dout, w0h, w08h, w08l, 0, i, B, gs[i], es[i]);
        __nv_bfloat16* yq_h = (i == 2) ? qh : qb_h;
        uint8_t* yq_8h = (i == 2) ? q8h : qb_8h;
        uint8_t* yq_8l = (i == 2) ? q8l : qb_8l;
        gemm_trunk<<<dim3(nx, B / 128), 256, GEMM_SMEM>>>(
            qa_h, qa_8h, qa_8l, w0h, w08h, w08l, bs[i],
            Din, Dout, accum_q, 0, i, yq_h, yq_8h, yq_8l);

        // k branch (s2)
        wprep_fused<<<dim3(Dout / 32, Din / 32), dim3(32, 8), 0, s2>>>(
            Ws[i], Din, Dout, w1h, w18h, w18l, 1, i, N, gs[i], es[i]);
        __nv_bfloat16* yk_h = (i == 2) ? kh : kb_h;
        uint8_t* yk_8h = (i == 2) ? k8h : kb_8h;
        uint8_t* yk_8l = (i == 2) ? k8l : kb_8l;
        gemm_trunk<<<dim3(nx, N / 128), 256, GEMM_SMEM, s2>>>(
            ka_h, ka_8h, ka_8l, w1h, w18h, w18l, bs[i],
            Din, Dout, accum_k, 1, i, yk_h, yk_8h, yk_8l);

        // swap ping-pong
        __nv_bfloat16* th;
        uint8_t* t8;
        th = qa_h; qa_h = qb_h; qb_h = th;
        t8 = qa_8h; qa_8h = qb_8h; qb_8h = t8;
        t8 = qa_8l; qa_8l = qb_8l; qb_8l = t8;
        th = ka_h; ka_h = kb_h; kb_h = th;
        t8 = ka_8h; ka_8h = kb_8h; kb_8h = t8;
        t8 = ka_8l; ka_8l = kb_8l; kb_8l = t8;
    }

    cudaEventRecord(evJoin, s2);
    cudaStreamWaitEvent(0, evJoin, 0);

    const int NSPLIT = N / 128;
    sim_flash<<<dim3(NSPLIT, B / 128), 256, GEMM_SMEM>>>(
        qh, q8h, q8l, kh, k8h, k8l, y, dims[3], NSPLIT);
    combine_out<<<B / 8, 256>>>((float*)d_out, NSPLIT);
}

// round 12
// speedup vs baseline: 1.2808x; 1.2808x over previous
#include <cuda_runtime.h>
#include <cuda_bf16.h>
#include <math.h>
#include <stdint.h>

// ===========================================================================
// Static scratch. Branch 0 = q (B=4096 rows), branch 1 = k (N=8192 rows).
// Stats: [branch][layer-slot 0..3][1024]; slot 0 = raw input stats,
// slot i+1 = stats of layer-i output. Bias: [branch][layer 0..2][1024].
// All pre-zeroed once by zero_all.
// ===========================================================================
__device__ float g_sum[2 * 4 * 1024];
__device__ float g_sumsq[2 * 4 * 1024];
__device__ float g_bias2[2 * 3 * 1024];
__device__ float g_k2[8192];
__device__ __nv_bfloat16 g_Q1h[4096 * 1024], g_Q1l[4096 * 1024];
__device__ __nv_bfloat16 g_Q2h[4096 * 1024], g_Q2l[4096 * 1024];
__device__ __nv_bfloat16 g_P1h[8192 * 1024], g_P1l[8192 * 1024];
__device__ __nv_bfloat16 g_P2h[8192 * 1024], g_P2l[8192 * 1024];
__device__ __nv_bfloat16 g_WT0h[1024 * 1024], g_WT0l[1024 * 1024];
__device__ __nv_bfloat16 g_WT1h[1024 * 1024], g_WT1l[1024 * 1024];
__device__ __nv_bfloat16 g_qh[4096 * 256], g_ql[4096 * 256];
__device__ __nv_bfloat16 g_kh[8192 * 256], g_kl[8192 * 256];
__device__ float g_pm[4096 * 64], g_pl[4096 * 64], g_pw[4096 * 64];

// ===========================================================================
// Prep kernels
// ===========================================================================
__global__ void zero_all() {
    int i = blockIdx.x * blockDim.x + threadIdx.x;   // 0..8191
    g_sum[i] = 0.f;
    g_sumsq[i] = 0.f;
    g_k2[i] = 0.f;
    if (i < 6144) g_bias2[i] = 0.f;
}

__global__ void split_stats_b(const float* __restrict__ X,
                              __nv_bfloat16* __restrict__ hi,
                              __nv_bfloat16* __restrict__ lo,
                              int R, int Din, int br) {
    int c = blockIdx.x * blockDim.x + threadIdx.x;
    if (c >= Din) return;
    int chunk = R / gridDim.y;
    int r0 = blockIdx.y * chunk;
    float s = 0.f, s2 = 0.f;
    for (int r = r0; r < r0 + chunk; ++r) {
        size_t i = (size_t)r * Din + c;
        float v = X[i];
        __nv_bfloat16 h = __float2bfloat16(v);
        hi[i] = h;
        lo[i] = __float2bfloat16(v - __bfloat162float(h));
        s += v;
        s2 = fmaf(v, v, s2);
    }
    atomicAdd(&g_sum[br * 4096 + c], s);     // slot 0
    atomicAdd(&g_sumsq[br * 4096 + c], s2);
}

// Fused: BN finalize (per-block, 32 k-cols) + WT transpose/scale/split +
// bias2 accumulation into per-(branch,layer) slot.
__global__ void wprep_fused(const float* __restrict__ W, int Din, int Dout,
                            __nv_bfloat16* __restrict__ WTh,
                            __nv_bfloat16* __restrict__ WTl,
                            int br, int layer, int R,
                            const float* __restrict__ gam,
                            const float* __restrict__ bet) {
    __shared__ float tile[32][33];
    __shared__ float sbias[8][32];
    __shared__ float sa[32], sdd[32];
    int k0 = blockIdx.y * 32, n0 = blockIdx.x * 32;
    int tx = threadIdx.x, ty = threadIdx.y;

    if (ty == 0) {
        int c = k0 + tx;
        int offs = (br * 4 + layer) * 1024;
        float inv = 1.0f / (float)R;
        float mean = g_sum[offs + c] * inv;
        float var = g_sumsq[offs + c] * inv - mean * mean;
        float a = gam[c] * rsqrtf(var + 1e-5f);
        sa[tx] = a;
        sdd[tx] = bet[c] - mean * a;
    }
    __syncthreads();

    float bp = 0.f;
    for (int i = ty; i < 32; i += 8) {
        float w = W[(size_t)(k0 + i) * Dout + n0 + tx];
        tile[i][tx] = sa[i] * w;
        bp = fmaf(sdd[i], w, bp);
    }
    sbias[ty][tx] = bp;
    __syncthreads();
    if (ty == 0) {
        float s = 0.f;
#pragma unroll
        for (int j = 0; j < 8; ++j) s += sbias[j][tx];
        atomicAdd(&g_bias2[(br * 3 + layer) * 1024 + n0 + tx], s);
    }
    for (int i = ty; i < 32; i += 8) {
        float v = tile[tx][i];
        size_t idx = (size_t)(n0 + i) * Din + (k0 + tx);
        __nv_bfloat16 h = __float2bfloat16(v);
        WTh[idx] = h;
        WTl[idx] = __float2bfloat16(v - __bfloat162float(h));
    }
}

// ===========================================================================
// GEMM machinery (R7 config): CTA 128x128, K-tile 32, 2-stage cp.async,
// 8 warps (2x4), warp tile 64x32, scalar LDS, 256 thr, 2 CTA/SM,
// 3-product bf16 emulation.
// ===========================================================================
#define LDKB 80
#define TILE_B (128 * LDKB)
#define STAGE_B (4 * TILE_B)
#define GEMM_SMEM (2 * STAGE_B)

__device__ __forceinline__ void mma_bf16(float* d, const uint32_t* a, const uint32_t* b) {
    asm volatile("mma.sync.aligned.m16n8k16.row.col.f32.bf16.bf16.f32 "
        "{%0,%1,%2,%3}, {%4,%5,%6,%7}, {%8,%9}, {%0,%1,%2,%3};"
        : "+f"(d[0]), "+f"(d[1]), "+f"(d[2]), "+f"(d[3])
        : "r"(a[0]), "r"(a[1]), "r"(a[2]), "r"(a[3]), "r"(b[0]), "r"(b[1]));
}

#define FILL_TILE(t, s)                                                        \
    do {                                                                       \
        char* base_ = smem + (s) * STAGE_B;                                    \
        const int k0_ = (t) << 5;                                              \
        _Pragma("unroll")                                                      \
        for (int l_ = 0; l_ < 8; ++l_) {                                       \
            int id_ = tid + (l_ << 8);                                         \
            int which_ = id_ >> 9;                                             \
            int e_ = id_ & 511;                                                \
            int row_ = e_ >> 2, c4_ = e_ & 3;                                  \
            const __nv_bfloat16* src_ =                                        \
                (which_ == 0) ? Ah : (which_ == 1) ? Al : (which_ == 2) ? Bh : Bl; \
            int grow_ = ((which_ < 2) ? m0 : n0) + row_;                       \
            const char* gp_ = (const char*)(src_ + (size_t)grow_ * K + k0_) + (c4_ << 4); \
            uint32_t sp_ = (uint32_t)__cvta_generic_to_shared(                 \
                base_ + which_ * TILE_B + row_ * LDKB + (c4_ << 4));           \
            asm volatile("cp.async.cg.shared.global [%0], [%1], 16;" :: "r"(sp_), "l"(gp_)); \
        }                                                                      \
        asm volatile("cp.async.commit_group;");                                \
    } while (0)

#define MMA_MAINLOOP()                                                         \
    do {                                                                       \
        FILL_TILE(0, 0);                                                       \
        for (int t = 0; t < T; ++t) {                                          \
            if (t + 1 < T) {                                                   \
                FILL_TILE(t + 1, (t + 1) & 1);                                 \
                asm volatile("cp.async.wait_group 1;");                        \
            } else {                                                           \
                asm volatile("cp.async.wait_group 0;");                        \
            }                                                                  \
            __syncthreads();                                                   \
            const char* st_ = smem + (t & 1) * STAGE_B;                        \
            _Pragma("unroll")                                                  \
            for (int kk = 0; kk < 2; ++kk) {                                   \
                const int kb_ = (kk << 4) + cc;                                \
                uint32_t bh_[4][2], bl_[4][2];                                 \
                _Pragma("unroll")                                              \
                for (int nt = 0; nt < 4; ++nt) {                               \
                    const char* pB_ = st_ + 2 * TILE_B + (wn * 32 + nt * 8 + g) * LDKB + kb_ * 2; \
                    bh_[nt][0] = *(const uint32_t*)pB_;                        \
                    bh_[nt][1] = *(const uint32_t*)(pB_ + 16);                 \
                    bl_[nt][0] = *(const uint32_t*)(pB_ + TILE_B);             \
                    bl_[nt][1] = *(const uint32_t*)(pB_ + TILE_B + 16);        \
                }                                                              \
                _Pragma("unroll")                                              \
                for (int mt = 0; mt < 4; ++mt) {                               \
                    const char* pA_ = st_ + (wm * 64 + mt * 16 + g) * LDKB + kb_ * 2; \
                    uint32_t ah_[4], al_[4];                                   \
                    ah_[0] = *(const uint32_t*)pA_;                            \
                    ah_[1] = *(const uint32_t*)(pA_ + 8 * LDKB);               \
                    ah_[2] = *(const uint32_t*)(pA_ + 16);                     \
                    ah_[3] = *(const uint32_t*)(pA_ + 8 * LDKB + 16);          \
                    al_[0] = *(const uint32_t*)(pA_ + TILE_B);                 \
                    al_[1] = *(const uint32_t*)(pA_ + TILE_B + 8 * LDKB);      \
                    al_[2] = *(const uint32_t*)(pA_ + TILE_B + 16);            \
                    al_[3] = *(const uint32_t*)(pA_ + TILE_B + 8 * LDKB + 16); \
                    _Pragma("unroll")                                          \
                    for (int nt = 0; nt < 4; ++nt) {                           \
                        mma_bf16(acc[mt][nt], ah_, bh_[nt]);                   \
                        mma_bf16(acc[mt][nt], ah_, bl_[nt]);                   \
                        mma_bf16(acc[mt][nt], al_, bh_[nt]);                   \
                    }                                                          \
                }                                                              \
            }                                                                  \
            __syncthreads();                                                   \
        }                                                                      \
    } while (0)

#define GEMM_THREAD_IDS()                                                      \
    const int tid = threadIdx.x;                                               \
    const int wid = tid >> 5, lane = tid & 31;                                 \
    const int g = lane >> 2;                                                   \
    const int cc = (lane & 3) * 2;                                             \
    const int wm = wid >> 2, wn = wid & 3;                                     \
    float acc[4][4][4];                                                        \
    _Pragma("unroll")                                                          \
    for (int i = 0; i < 4; ++i)                                                \
        _Pragma("unroll")                                                      \
        for (int j = 0; j < 4; ++j)                                            \
            _Pragma("unroll")                                                  \
            for (int r = 0; r < 4; ++r) acc[i][j][r] = 0.f;

// ===========================================================================
// Trunk GEMM. bias = g_bias2[br][layer] + bvec. accum 1: col stats of tanh
// -> g_sum/g_sumsq slot layer+1; accum 2: row sumsq -> g_k2.
// ===========================================================================
__global__ __launch_bounds__(256, 2) void gemm_trunk(
    const __nv_bfloat16* __restrict__ Ah, const __nv_bfloat16* __restrict__ Al,
    const __nv_bfloat16* __restrict__ Bh, const __nv_bfloat16* __restrict__ Bl,
    const float* __restrict__ bvec,
    int K, int ldOut, int accum, int br, int layer,
    __nv_bfloat16* __restrict__ Yh, __nv_bfloat16* __restrict__ Yl)
{
    extern __shared__ __align__(16) char smem[];
    GEMM_THREAD_IDS();
    const int m0 = blockIdx.y * 128, n0 = blockIdx.x * 128;
    const int T = K >> 5;
    const float* bias = g_bias2 + (br * 3 + layer) * 1024;

    MMA_MAINLOOP();

    float* s_sum = (float*)smem;
    float* s_sq  = (float*)smem + 128;
    if (accum) {
        if (tid < 128) { s_sum[tid] = 0.f; s_sq[tid] = 0.f; }
        __syncthreads();
    }

#pragma unroll
    for (int mt = 0; mt < 4; ++mt) {
#pragma unroll
        for (int nt = 0; nt < 4; ++nt) {
            int row = m0 + wm * 64 + mt * 16 + g;
            int col = n0 + wn * 32 + nt * 8 + cc;
            float* a = acc[mt][nt];
            float bA = bias[col] + bvec[col];
            float bB = bias[col + 1] + bvec[col + 1];
#pragma unroll
            for (int h = 0; h < 2; ++h) {
                int r = row + h * 8;
                float v0 = tanhf(a[h * 2 + 0] + bA);
                float v1 = tanhf(a[h * 2 + 1] + bB);
                a[h * 2 + 0] = v0;
                a[h * 2 + 1] = v1;
                __nv_bfloat162 hp, lp;
                hp.x = __float2bfloat16(v0);
                hp.y = __float2bfloat16(v1);
                lp.x = __float2bfloat16(v0 - __bfloat162float(hp.x));
                lp.y = __float2bfloat16(v1 - __bfloat162float(hp.y));
                *(uint32_t*)(Yh + (size_t)r * ldOut + col) = *(uint32_t*)&hp;
                *(uint32_t*)(Yl + (size_t)r * ldOut + col) = *(uint32_t*)&lp;
            }
        }
    }

    if (accum == 1) {
#pragma unroll
        for (int nt = 0; nt < 4; ++nt) {
            int lc = wn * 32 + nt * 8 + cc;
            float s0 = 0.f, q0 = 0.f, s1 = 0.f, q1 = 0.f;
#pragma unroll
            for (int mt = 0; mt < 4; ++mt) {
                float* a = acc[mt][nt];
#pragma unroll
                for (int h = 0; h < 2; ++h) {
                    s0 += a[h * 2 + 0]; q0 = fmaf(a[h * 2 + 0], a[h * 2 + 0], q0);
                    s1 += a[h * 2 + 1]; q1 = fmaf(a[h * 2 + 1], a[h * 2 + 1], q1);
                }
            }
            atomicAdd(&s_sum[lc], s0);     atomicAdd(&s_sq[lc], q0);
            atomicAdd(&s_sum[lc + 1], s1); atomicAdd(&s_sq[lc + 1], q1);
        }
        __syncthreads();
        if (tid < 128) {
            int offs = (br * 4 + layer + 1) * 1024 + n0 + tid;
            atomicAdd(&g_sum[offs], s_sum[tid]);
            atomicAdd(&g_sumsq[offs], s_sq[tid]);
        }
    } else if (accum == 2) {
#pragma unroll
        for (int mt = 0; mt < 4; ++mt) {
#pragma unroll
            for (int h = 0; h < 2; ++h) {
                int lr = wm * 64 + mt * 16 + h * 8 + g;
                float s = 0.f;
#pragma unroll
                for (int nt = 0; nt < 4; ++nt) {
                    float v0 = acc[mt][nt][h * 2 + 0];
                    float v1 = acc[mt][nt][h * 2 + 1];
                    s = fmaf(v0, v0, s);
                    s = fmaf(v1, v1, s);
                }
                atomicAdd(&s_sum[lr], s);
            }
        }
        __syncthreads();
        if (tid < 128) atomicAdd(&g_k2[m0 + tid], s_sum[tid]);
    }
}

// ===========================================================================
// Flash sim+softmax
// ===========================================================================
__global__ __launch_bounds__(256, 2) void sim_flash(
    const __nv_bfloat16* __restrict__ Ah, const __nv_bfloat16* __restrict__ Al,
    const __nv_bfloat16* __restrict__ Bh, const __nv_bfloat16* __restrict__ Bl,
    const float* __restrict__ y, int K, int nsplit)
{
    extern __shared__ __align__(16) char smem[];
    GEMM_THREAD_IDS();
    const int m0 = blockIdx.y * 128, n0 = blockIdx.x * 128;
    const int T = K >> 5;
    MMA_MAINLOOP();

    float yv[4][2], k2v[4][2];
#pragma unroll
    for (int nt = 0; nt < 4; ++nt) {
        int col = n0 + wn * 32 + nt * 8 + cc;
        yv[nt][0] = y[col];     yv[nt][1] = y[col + 1];
        k2v[nt][0] = g_k2[col]; k2v[nt][1] = g_k2[col + 1];
    }

    float* red = (float*)smem;
#pragma unroll
    for (int mt = 0; mt < 4; ++mt) {
#pragma unroll
        for (int h = 0; h < 2; ++h) {
            float lg[4][2];
            float mx = -3.4e38f;
#pragma unroll
            for (int nt = 0; nt < 4; ++nt) {
#pragma unroll
                for (int c2 = 0; c2 < 2; ++c2) {
                    float v = 2.f * acc[mt][nt][h * 2 + c2] - k2v[nt][c2];
                    lg[nt][c2] = v;
                    mx = fmaxf(mx, v);
                }
            }
            mx = fmaxf(mx, __shfl_xor_sync(0xFFFFFFFF, mx, 1));
            mx = fmaxf(mx, __shfl_xor_sync(0xFFFFFFFF, mx, 2));
            float s = 0.f, w = 0.f;
#pragma unroll
            for (int nt = 0; nt < 4; ++nt) {
#pragma unroll
                for (int c2 = 0; c2 < 2; ++c2) {
                    float e = __expf(lg[nt][c2] - mx);
                    s += e;
                    w = fmaf(e, yv[nt][c2], w);
                }
            }
            s += __shfl_xor_sync(0xFFFFFFFF, s, 1);
            s += __shfl_xor_sync(0xFFFFFFFF, s, 2);
            w += __shfl_xor_sync(0xFFFFFFFF, w, 1);
            w += __shfl_xor_sync(0xFFFFFFFF, w, 2);
            if ((lane & 3) == 0) {
                int lr = wm * 64 + mt * 16 + h * 8 + g;
                red[(lr * 4 + wn) * 3 + 0] = mx;
                red[(lr * 4 + wn) * 3 + 1] = s;
                red[(lr * 4 + wn) * 3 + 2] = w;
            }
        }
    }
    __syncthreads();
    if (tid < 128) {
        float M = -3.4e38f;
#pragma unroll
        for (int j = 0; j < 4; ++j) M = fmaxf(M, red[(tid * 4 + j) * 3 + 0]);
        float L = 0.f, W = 0.f;
#pragma unroll
        for (int j = 0; j < 4; ++j) {
            float e = __expf(red[(tid * 4 + j) * 3 + 0] - M);
            L = fmaf(red[(tid * 4 + j) * 3 + 1], e, L);
            W = fmaf(red[(tid * 4 + j) * 3 + 2], e, W);
        }
        size_t idx = (size_t)(m0 + tid) * nsplit + blockIdx.x;
        g_pm[idx] = M;
        g_pl[idx] = L;
        g_pw[idx] = W;
    }
}

__global__ void combine_out(float* __restrict__ out, int S) {
    int row = blockIdx.x * 8 + (threadIdx.x >> 5);
    int lane = threadIdx.x & 31;
    size_t base = (size_t)row * S;
    float m1 = g_pm[base + lane], m2 = g_pm[base + lane + 32];
    float l1 = g_pl[base + lane], l2 = g_pl[base + lane + 32];
    float w1 = g_pw[base + lane], w2 = g_pw[base + lane + 32];
    float M = fmaxf(m1, m2);
#pragma unroll
    for (int o = 16; o > 0; o >>= 1)
        M = fmaxf(M, __shfl_xor_sync(0xFFFFFFFF, M, o));
    float L = l1 * __expf(m1 - M) + l2 * __expf(m2 - M);
    float W = w1 * __expf(m1 - M) + w2 * __expf(m2 - M);
#pragma unroll
    for (int o = 16; o > 0; o >>= 1) {
        L += __shfl_xor_sync(0xFFFFFFFF, L, o);
        W += __shfl_xor_sync(0xFFFFFFFF, W, o);
    }
    if (lane == 0) {
        float r = W / L;
        out[row] = fminf(fmaxf(r, 0.f), 1.f);
    }
}

// ===========================================================================
// Host launcher — fork/join. k branch (critical path, 2x work) on the
// default/capture stream and launched first each layer; q branch on s2.
// ===========================================================================
extern "C" void kernel_launch(void* const* d_in, const int* in_sizes, int n_in,
                              void* d_out, int out_size)
{
    const float* x   = (const float*)d_in[0];
    const float* xn  = (const float*)d_in[1];
    const float* y   = (const float*)d_in[2];
    const float* Ws[3] = {(const float*)d_in[3], (const float*)d_in[7], (const float*)d_in[11]};
    const float* bs[3] = {(const float*)d_in[4], (const float*)d_in[8], (const float*)d_in[12]};
    const float* gs[3] = {(const float*)d_in[5], (const float*)d_in[9], (const float*)d_in[13]};
    const float* es[3] = {(const float*)d_in[6], (const float*)d_in[10], (const float*)d_in[14]};

    const int D  = in_sizes[5];
    const int B  = in_sizes[0] / D;      // 4096
    const int N  = in_sizes[2];          // 8192
    const int dims[4] = {D, in_sizes[4], in_sizes[8], in_sizes[12]};

    __nv_bfloat16 *q1h, *q1l, *q2h, *q2l, *p1h, *p1l, *p2h, *p2l;
    __nv_bfloat16 *w0h, *w0l, *w1h, *w1l, *qh, *ql, *kh, *kl;
    cudaGetSymbolAddress((void**)&q1h, g_Q1h); cudaGetSymbolAddress((void**)&q1l, g_Q1l);
    cudaGetSymbolAddress((void**)&q2h, g_Q2h); cudaGetSymbolAddress((void**)&q2l, g_Q2l);
    cudaGetSymbolAddress((void**)&p1h, g_P1h); cudaGetSymbolAddress((void**)&p1l, g_P1l);
    cudaGetSymbolAddress((void**)&p2h, g_P2h); cudaGetSymbolAddress((void**)&p2l, g_P2l);
    cudaGetSymbolAddress((void**)&w0h, g_WT0h); cudaGetSymbolAddress((void**)&w0l, g_WT0l);
    cudaGetSymbolAddress((void**)&w1h, g_WT1h); cudaGetSymbolAddress((void**)&w1l, g_WT1l);
    cudaGetSymbolAddress((void**)&qh, g_qh);   cudaGetSymbolAddress((void**)&ql, g_ql);
    cudaGetSymbolAddress((void**)&kh, g_kh);   cudaGetSymbolAddress((void**)&kl, g_kl);

    cudaFuncSetAttribute(gemm_trunk, cudaFuncAttributeMaxDynamicSharedMemorySize, GEMM_SMEM);
    cudaFuncSetAttribute(sim_flash, cudaFuncAttributeMaxDynamicSharedMemorySize, GEMM_SMEM);

    static cudaStream_t s2 = nullptr;
    static cudaEvent_t evFork = nullptr, evJoin = nullptr;
    if (s2 == nullptr) {
        cudaStreamCreateWithFlags(&s2, cudaStreamNonBlocking);
        cudaEventCreateWithFlags(&evFork, cudaEventDisableTiming);
        cudaEventCreateWithFlags(&evJoin, cudaEventDisableTiming);
    }

    zero_all<<<32, 256>>>();
    cudaEventRecord(evFork, 0);
    cudaStreamWaitEvent(s2, evFork, 0);

    // k branch (branch 1) on default stream — critical path; q (branch 0) on s2.
    split_stats_b<<<dim3(D / 256, 64), 256>>>(xn, p1h, p1l, N, D, 1);
    split_stats_b<<<dim3(D / 256, 64), 256, 0, s2>>>(x, q1h, q1l, B, D, 0);

    __nv_bfloat16 *qa_h = q1h, *qa_l = q1l, *qb_h = q2h, *qb_l = q2l;
    __nv_bfloat16 *ka_h = p1h, *ka_l = p1l, *kb_h = p2h, *kb_l = p2l;

    for (int i = 0; i < 3; ++i) {
        int Din = dims[i], Dout = dims[i + 1];
        int nx = Dout / 128;
        int accum_q = (i < 2) ? 1 : 0;
        int accum_k = (i < 2) ? 1 : 2;

        // k branch first (default stream — critical path)
        wprep_fused<<<dim3(Dout / 32, Din / 32), dim3(32, 8)>>>(
            Ws[i], Din, Dout, w1h, w1l, 1, i, N, gs[i], es[i]);
        __nv_bfloat16* yk_h = (i == 2) ? kh : kb_h;
        __nv_bfloat16* yk_l = (i == 2) ? kl : kb_l;
        gemm_trunk<<<dim3(nx, N / 128), 256, GEMM_SMEM>>>(
            ka_h, ka_l, w1h, w1l, bs[i], Din, Dout, accum_k, 1, i, yk_h, yk_l);

        // q branch (s2)
        wprep_fused<<<dim3(Dout / 32, Din / 32), dim3(32, 8), 0, s2>>>(
            Ws[i], Din, Dout, w0h, w0l, 0, i, B, gs[i], es[i]);
        __nv_bfloat16* yq_h = (i == 2) ? qh : qb_h;
        __nv_bfloat16* yq_l = (i == 2) ? ql : qb_l;
        gemm_trunk<<<dim3(nx, B / 128), 256, GEMM_SMEM, s2>>>(
            qa_h, qa_l, w0h, w0l, bs[i], Din, Dout, accum_q, 0, i, yq_h, yq_l);

        __nv_bfloat16* t;
        t = qa_h; qa_h = qb_h; qb_h = t;  t = qa_l; qa_l = qb_l; qb_l = t;
        t = ka_h; ka_h = kb_h; kb_h = t;  t = ka_l; ka_l = kb_l; kb_l = t;
    }

    // join: default stream (k chain) waits for q chain
    cudaEventRecord(evJoin, s2);
    cudaStreamWaitEvent(0, evJoin, 0);

    const int NSPLIT = N / 128;
    sim_flash<<<dim3(NSPLIT, B / 128), 256, GEMM_SMEM>>>(
        qh, ql, kh, kl, y, dims[3], NSPLIT);
    combine_out<<<B / 8, 256>>>((float*)d_out, NSPLIT);
}